// round 14
// baseline (speedup 1.0000x reference)
#include <cuda_runtime.h>
#include <cuda_fp16.h>
#include <cstdint>

// ================= scratch (static device globals) =================
__device__ __align__(16) __half g_xth   [64L*4096*32];   // x [img][p][cin], fp16
__device__ __align__(16) float  g_y0t   [64L*4096*192];  // conv0 out [img][p][cout] (gate|hid|res)
__device__ __align__(16) float  g_out0t [64L*4096*64];   // layer0 out (fp32, residual)
__device__ __align__(16) __half g_out0tfh[64L*4096*64];  // layer0 out, fp16 (conv1 B input)
__device__ __align__(16) float  g_y1t   [64L*4096*128];  // conv1 out [img][p][cout] (gate|hid)
__device__ __align__(16) __half g_A0h   [9*4096 + 9*2048]; // conv0 W: [ck][row128][cin32] ++ [ck][row64][cin32]
__device__ __align__(16) __half g_A1h   [18*4096];         // conv1 W: [ck][row128][cin32] (ck = tap*2+half)

// ================= helpers =================
static __device__ __forceinline__ uint32_t s2u(const void* p) {
    uint32_t a;
    asm("{ .reg .u64 t; cvta.to.shared.u64 t, %1; cvt.u32.u64 %0, t; }" : "=r"(a) : "l"(p));
    return a;
}
static __device__ __forceinline__ void cp16(uint32_t daddr, const void* gptr, bool pred) {
    int sz = pred ? 16 : 0;
    asm volatile("cp.async.ca.shared.global [%0], [%1], 16, %2;"
                 :: "r"(daddr), "l"(gptr), "r"(sz));
}
static __device__ __forceinline__ void mma_f16(float& d0, float& d1, float& d2, float& d3,
                                               uint32_t a0, uint32_t a1, uint32_t a2, uint32_t a3,
                                               uint32_t b0, uint32_t b1) {
    asm volatile("mma.sync.aligned.m16n8k16.row.col.f32.f16.f16.f32 "
                 "{%0,%1,%2,%3}, {%4,%5,%6,%7}, {%8,%9}, {%0,%1,%2,%3};"
                 : "+f"(d0), "+f"(d1), "+f"(d2), "+f"(d3)
                 : "r"(a0), "r"(a1), "r"(a2), "r"(a3), "r"(b0), "r"(b1));
}
#define LDSM4(r0, r1, r2, r3, addr) \
    asm volatile("ldmatrix.sync.aligned.m8n8.x4.shared.b16 {%0,%1,%2,%3}, [%4];" \
                 : "=r"(r0), "=r"(r1), "=r"(r2), "=r"(r3) : "r"(addr))

// ================= pre-processing =================
// x [img][32][4096] -> g_xth [img][p][cin]  (fp16)
__global__ void transpose_x(const float* __restrict__ x) {
    __shared__ float s[32][137];
    const int img = blockIdx.y, p0 = blockIdx.x * 128, t = threadIdx.x;
    const int c8 = t >> 5, pq = t & 31;
    for (int cc = c8; cc < 32; cc += 8) {
        float4 v = *(const float4*)(x + ((size_t)img * 32 + cc) * 4096 + p0 + pq * 4);
        s[cc][pq*4+0] = v.x; s[cc][pq*4+1] = v.y; s[cc][pq*4+2] = v.z; s[cc][pq*4+3] = v.w;
    }
    __syncthreads();
    const int pl = t >> 3, cq = t & 7;
    for (int pp = pl; pp < 128; pp += 32) {
        __half2 h01 = __floats2half2_rn(s[cq*4+0][pp], s[cq*4+1][pp]);
        __half2 h23 = __floats2half2_rn(s[cq*4+2][pp], s[cq*4+3][pp]);
        __half2* dst = (__half2*)(g_xth + ((size_t)img * 4096 + p0 + pp) * 32 + cq * 4);
        dst[0] = h01; dst[1] = h23;
    }
}

// conv0 weights: tile0 [ck][row128][cin32] (W0), tile1 [ck][row64][cin32] (R0), fp16
__global__ void packA0(const float* __restrict__ W0, const float* __restrict__ R0) {
    int idx = blockIdx.x * 256 + threadIdx.x;       // 55296 total
    if (idx >= 9*4096 + 9*2048) return;
    if (idx < 9*4096) {
        const int ck  = idx >> 12;
        const int row = (idx >> 5) & 127;
        const int cin = idx & 31;
        g_A0h[idx] = __float2half_rn(W0[row * 288 + cin * 9 + ck]);
    } else {
        const int i2  = idx - 9*4096;
        const int ck  = i2 >> 11;
        const int row = (i2 >> 5) & 63;
        const int cin = i2 & 31;
        g_A0h[idx] = __float2half_rn(R0[row * 288 + cin * 9 + ck]);
    }
}
__global__ void packA1(const float* __restrict__ W1) {
    int idx = blockIdx.x * 256 + threadIdx.x;       // 73728
    if (idx >= 18*4096) return;
    const int ck  = idx >> 12;
    const int row = (idx >> 5) & 127;
    const int cl  = idx & 31;
    const int tap = ck >> 1;
    const int cin = ((ck & 1) << 5) + cl;
    g_A1h[idx] = __float2half_rn(W1[row * 576 + cin * 9 + tap]);
}

// ================= fp16 HMMA implicit-GEMM conv, A-resident smem, barrier-free mainloop ====
// CTA: (MFR*32) couts x 128 pixels (2 image rows), 128 threads (4 warps: 2m x 2n).
// Per phase: halo (4x66 px) + ALL 9 A chunks loaded into smem in 2 cp.async groups;
// compute runs with only 2 wait+sync points, chunks back-to-back (no per-chunk barriers).
// Pitch 40 halves (80B rows, 16B-aligned): LDSM row word-offsets r*20 mod 32 distinct.
#define PIT 40
#define HALO_H (4*66*PIT)             // 10560 halves (21120 B)

template<int MFR, int C, int NCH>
__global__ __launch_bounds__(128) void conv_tc(int which, const float* __restrict__ bias) {
    constexpr int ROWS = MFR * 32;                 // CTA M
    constexpr int ACH  = ROWS * PIT;               // halves per A chunk slot
    constexpr int PH   = (NCH == 9) ? 1 : 2;       // cin phases
    constexpr int EPIP = MFR * 32 + 4;

    extern __shared__ __align__(16) float smem_f[];

    const int tid  = threadIdx.x;
    const int lane = tid & 31;
    const int wid  = tid >> 5;
    const int wm   = wid >> 1;        // 0..1
    const int wn   = wid & 1;         // 0..1 = image row within pair

    const __half* Aw; const __half* Xt; float* Y; int m0, CoutS;
    if (which == 0)      { Aw = g_A0h;          Xt = g_xth;      Y = g_y0t; m0 = 0;   CoutS = 192; }
    else if (which == 1) { Aw = g_A0h + 9*4096; Xt = g_xth;      Y = g_y0t; m0 = 128; CoutS = 192; }
    else                 { Aw = g_A1h;          Xt = g_out0tfh;  Y = g_y1t; m0 = 0;   CoutS = 128; }

    const int img = blockIdx.z;
    const int n0  = blockIdx.x * 128;             // pixel base (2 image rows)
    const int y0  = blockIdx.x * 2;
    const __half* Ximg = Xt + (size_t)img * 4096 * C;
    const uint32_t sb  = s2u(smem_f);
    const uint32_t sbH = sb;
    const uint32_t sbA = sb + HALO_H * 2;

    float acc[MFR][8][4];
    #pragma unroll
    for (int a = 0; a < MFR; a++)
        #pragma unroll
        for (int b = 0; b < 8; b++)
            #pragma unroll
            for (int c = 0; c < 4; c++) acc[a][b][c] = 0.0f;

    // zero x-halo columns (px slots 0 and 65): 4 rows x 2 slots x 5 uint4 (40 halves)
    if (tid < 40) {
        const int hr = tid / 10, rest = tid % 10, cs = rest / 5, q = rest % 5;
        const uint4 z = make_uint4(0, 0, 0, 0);
        *(uint4*)((char*)smem_f + ((hr*66 + (cs ? 65 : 0)) * PIT + q * 8) * 2) = z;
    }

    // ---- halo load for cin-phase h: rows y0-1..y0+2, 64 px, 32 halves each ----
    auto load_halo = [&](int h) {
        #pragma unroll
        for (int it = 0; it < 8; it++) {
            const int i  = tid + it * 128;        // 1024 cp16
            const int hr = i >> 8;
            const int rm = i & 255;
            const int px = rm >> 2, q = rm & 3;
            const int yy = y0 - 1 + hr;
            const bool ok = (unsigned)yy < 64u;
            cp16(sbH + ((hr*66 + 1 + px) * PIT + q * 8) * 2,
                 Ximg + ((size_t)(yy * 64 + px)) * C + h * 32 + q * 8, ok);
        }
    };
    // ---- copy A chunks [lo, hi) of phase ph into resident smem slots ----
    auto prefA = [&](int ph, int lo, int hi) {
        for (int l = lo; l < hi; l++) {
            const int ckA = (NCH == 9) ? l : (l * 2 + ph);
            const __half* asrc = Aw + (size_t)ckA * (ROWS * 32);
            const uint32_t ab = sbA + (uint32_t)l * (ACH * 2);
            #pragma unroll
            for (int it = 0; it < MFR; it++) {     // ROWS*4 cp16 over 128 threads
                const int idx = tid + it * 128;
                const int row = idx >> 2, q = idx & 3;
                cp16(ab + (row * PIT + q * 8) * 2, asrc + row * 32 + q * 8, true);
            }
        }
    };

    // ldmatrix lane-address components (R12-verified): g&1 -> +8 rows, g>>1 -> +8 halves
    const int lg = lane >> 3, li = lane & 7;
    const int mrow = ((lg & 1) << 3) + li;
    const int mcol = (lg >> 1) << 3;              // halves

    for (int ph = 0; ph < PH; ph++) {
        if (ph > 0) __syncthreads();               // prior-phase smem reads complete
        load_halo(ph);
        prefA(ph, 0, 4);
        asm volatile("cp.async.commit_group;" ::: "memory");
        prefA(ph, 4, 9);
        asm volatile("cp.async.commit_group;" ::: "memory");

        #pragma unroll
        for (int half = 0; half < 2; half++) {
            if (half == 0) asm volatile("cp.async.wait_group 1;" ::: "memory");
            else           asm volatile("cp.async.wait_group 0;" ::: "memory");
            __syncthreads();
            const int lo = half ? 4 : 0, hi = half ? 9 : 4;
            #pragma unroll 1
            for (int l = lo; l < hi; l++) {
                const int r = l / 3 - 1;
                const int s = l - (l / 3) * 3 - 1;
                const uint32_t a_th = sbA + (uint32_t)l * (ACH * 2) +
                                      ((wm * (MFR*16) + mrow) * PIT + mcol) * 2;
                const uint32_t b_th = sbH + (((wn + 1 + r) * 66 + 1 + s + mrow) * PIT + mcol) * 2;
                #pragma unroll
                for (int kst = 0; kst < 2; kst++) {
                    uint32_t afr[MFR][4];
                    #pragma unroll
                    for (int mf = 0; mf < MFR; mf++)
                        LDSM4(afr[mf][0], afr[mf][1], afr[mf][2], afr[mf][3],
                              a_th + (mf * 16 * PIT + kst * 16) * 2);
                    #pragma unroll
                    for (int nfp = 0; nfp < 4; nfp++) {
                        uint32_t b0, b1, b2, b3;
                        LDSM4(b0, b1, b2, b3, b_th + (nfp * 16 * PIT + kst * 16) * 2);
                        #pragma unroll
                        for (int mf = 0; mf < MFR; mf++) {
                            mma_f16(acc[mf][nfp*2][0],   acc[mf][nfp*2][1],
                                    acc[mf][nfp*2][2],   acc[mf][nfp*2][3],
                                    afr[mf][0], afr[mf][1], afr[mf][2], afr[mf][3], b0, b2);
                            mma_f16(acc[mf][nfp*2+1][0], acc[mf][nfp*2+1][1],
                                    acc[mf][nfp*2+1][2], acc[mf][nfp*2+1][3],
                                    afr[mf][0], afr[mf][1], afr[mf][2], afr[mf][3], b1, b3);
                        }
                    }
                }
            }
        }
    }
    __syncthreads();   // all smem reads done before epilogue reuses the buffer

    // ---- epilogue: two pixel-halves through smem, coalesced stores (R10-12-verified) ----
    {
        float* sm = smem_f;
        float* Yimg = Y + (size_t)img * 4096 * CoutS;
        constexpr int mq = MFR * 8;       // f4 per pixel row
        #pragma unroll
        for (int half = 0; half < 2; half++) {
            if (wn == half) {
                #pragma unroll
                for (int mf = 0; mf < MFR; mf++) {
                    const int r0 = wm * (MFR * 16) + mf * 16 + (lane >> 2);
                    const int c0 = m0 + r0;
                    const float bv0 = (c0     < 128) ? bias[c0]     : 0.0f;
                    const float bv1 = (c0 + 8 < 128) ? bias[c0 + 8] : 0.0f;
                    #pragma unroll
                    for (int nf = 0; nf < 8; nf++) {
                        const int cc = nf * 8 + (lane & 3) * 2;   // 0..63 within half
                        sm[cc       * EPIP + r0]     = acc[mf][nf][0] + bv0;
                        sm[(cc + 1) * EPIP + r0]     = acc[mf][nf][1] + bv0;
                        sm[cc       * EPIP + r0 + 8] = acc[mf][nf][2] + bv1;
                        sm[(cc + 1) * EPIP + r0 + 8] = acc[mf][nf][3] + bv1;
                    }
                }
            }
            __syncthreads();
            for (int idx = tid; idx < 64 * mq; idx += 128) {
                const int pxl = idx / mq;
                const int j   = idx - pxl * mq;
                const float4 v = *(const float4*)&sm[pxl * EPIP + j * 4];
                *(float4*)&Yimg[(size_t)(n0 + half * 64 + pxl) * CoutS + m0 + j * 4] = v;
            }
            __syncthreads();
        }
    }
}

// ================= scans =================
static __device__ __forceinline__ float sigm(float x) { return 1.0f / (1.0f + __expf(-x)); }

// layer0: reads y0t [img][p][192], writes out0t (fp32) + out0tfh (fp16) + h0
__global__ void scan0_kernel(float* __restrict__ out) {
    const int g = blockIdx.x * 256 + threadIdx.x;    // 1,048,576
    const int c = g & 63;
    const int p = (g >> 6) & 4095;
    const int b = g >> 18;
    float h = 0.5f;
    #pragma unroll 1
    for (int t = 0; t < 16; t++) {
        const size_t base = ((size_t)(b * 16 + t) * 4096 + p) * 192;
        const float gate = g_y0t[base + c];
        const float hid  = g_y0t[base + 64 + c];
        const float res  = g_y0t[base + 128 + c];
        const float z  = sigm(gate);
        const float a  = sigm(-gate);
        const float gv = (hid >= 0.0f) ? (hid + 0.5f) : sigm(hid);
        h = a * h + z * gv;
        const float o = h + res;
        const size_t oidx = ((size_t)(b * 16 + t) * 4096 + p) * 64 + c;
        g_out0t  [oidx] = o;
        g_out0tfh[oidx] = __float2half_rn(o);
    }
    out[16777216 + ((size_t)b * 64 + c) * 4096 + p] = h;   // h0 [b][c][p]
}

// layer1: reads y1t [img][p][128] + out0t; writes final out [img][c][p] + h1
__global__ void scan1_kernel(float* __restrict__ out) {
    __shared__ __align__(16) float st[64][68];
    const int t  = threadIdx.x;
    const int pb = blockIdx.x;        // 0..63
    const int b  = blockIdx.y;        // 0..3
    const int p0 = pb * 64;
    const int pl = t >> 2, qb = t & 3;
    const int co = t >> 2, pq = t & 3;
    float h[16];
    #pragma unroll
    for (int i = 0; i < 16; i++) h[i] = 0.5f;

    #pragma unroll 1
    for (int ts = 0; ts < 16; ts++) {
        const int img = b * 16 + ts;
        const size_t rb = (size_t)img * 4096 + p0 + pl;
        #pragma unroll
        for (int j = 0; j < 4; j++) {
            const int c0 = qb * 4 + 16 * j;
            const float4 g4 = *(const float4*)(g_y1t   + rb * 128 + c0);
            const float4 d4 = *(const float4*)(g_y1t   + rb * 128 + 64 + c0);
            const float4 i4 = *(const float4*)(g_out0t + rb * 64 + c0);
            const float gv4[4] = {g4.x, g4.y, g4.z, g4.w};
            const float dv4[4] = {d4.x, d4.y, d4.z, d4.w};
            const float iv4[4] = {i4.x, i4.y, i4.z, i4.w};
            #pragma unroll
            for (int e = 0; e < 4; e++) {
                const float z  = sigm(gv4[e]);
                const float a  = sigm(-gv4[e]);
                const float gg = (dv4[e] >= 0.0f) ? (dv4[e] + 0.5f) : sigm(dv4[e]);
                float hh = a * h[j * 4 + e] + z * gg;
                h[j * 4 + e] = hh;
                st[c0 + e][pl] = hh + iv4[e];
            }
        }
        __syncthreads();
        #pragma unroll
        for (int i = 0; i < 4; i++) {
            const float4 v = *(const float4*)&st[co][pq * 16 + 4 * i];
            *(float4*)(out + ((size_t)img * 64 + co) * 4096 + p0 + pq * 16 + 4 * i) = v;
        }
        __syncthreads();
    }
    #pragma unroll
    for (int j = 0; j < 4; j++)
        #pragma unroll
        for (int e = 0; e < 4; e++)
            st[qb * 4 + 16 * j + e][pl] = h[j * 4 + e];
    __syncthreads();
    #pragma unroll
    for (int i = 0; i < 4; i++) {
        const float4 v = *(const float4*)&st[co][pq * 16 + 4 * i];
        *(float4*)(out + 17825792 + ((size_t)b * 64 + co) * 4096 + p0 + pq * 16 + 4 * i) = v;
    }
}

// ================= launch =================
extern "C" void kernel_launch(void* const* d_in, const int* in_sizes, int n_in,
                              void* d_out, int out_size) {
    const float* x  = (const float*)d_in[0];
    const float* W0 = (const float*)d_in[1];
    const float* b0 = (const float*)d_in[2];
    const float* R0 = (const float*)d_in[3];
    const float* W1 = (const float*)d_in[4];
    const float* b1 = (const float*)d_in[5];
    float* out = (float*)d_out;

    const int smem4 = (HALO_H + 9 * 128 * PIT) * 2;   // 113280 B
    const int smem2 = (HALO_H + 9 *  64 * PIT) * 2;   // 67200 B
    cudaFuncSetAttribute(conv_tc<4,32,9>,  cudaFuncAttributeMaxDynamicSharedMemorySize, smem4);
    cudaFuncSetAttribute(conv_tc<2,32,9>,  cudaFuncAttributeMaxDynamicSharedMemorySize, smem2);
    cudaFuncSetAttribute(conv_tc<4,64,18>, cudaFuncAttributeMaxDynamicSharedMemorySize, smem4);

    transpose_x<<<dim3(32, 64), 256>>>(x);
    packA0<<<216, 256>>>(W0, R0);
    packA1<<<288, 256>>>(W1);

    conv_tc<4,32,9><<<dim3(32, 1, 64), 128, smem4>>>(0, b0);   // conv0 couts 0..127 (W0)
    conv_tc<2,32,9><<<dim3(32, 1, 64), 128, smem2>>>(1, b0);   // conv0 couts 128..191 (R0)
    scan0_kernel<<<4096, 256>>>(out);
    conv_tc<4,64,18><<<dim3(32, 1, 64), 128, smem4>>>(2, b1);  // conv1
    scan1_kernel<<<dim3(64, 4), 256>>>(out);
}

// round 15
// speedup vs baseline: 1.0615x; 1.0615x over previous
#include <cuda_runtime.h>
#include <cuda_fp16.h>
#include <cstdint>

// ================= scratch (static device globals) =================
__device__ __align__(16) __half g_xth   [64L*4096*32];   // x [img][p][cin], fp16
__device__ __align__(16) float  g_y0t   [64L*4096*192];  // conv0 out [img][p][cout] (gate|hid|res)
__device__ __align__(16) float  g_out0t [64L*4096*64];   // layer0 out (fp32, residual)
__device__ __align__(16) __half g_out0tfh[64L*4096*64];  // layer0 out, fp16 (conv1 B input)
__device__ __align__(16) float  g_y1t   [64L*4096*128];  // conv1 out [img][p][cout] (gate|hid)
__device__ __align__(16) __half g_A0h   [9*4096 + 9*2048]; // conv0 W: [ck][row128][cin32] ++ [ck][row64][cin32]
__device__ __align__(16) __half g_A1h   [18*4096];         // conv1 W: [ck][row128][cin32] (ck = tap*2+half)

// ================= helpers =================
static __device__ __forceinline__ uint32_t s2u(const void* p) {
    uint32_t a;
    asm("{ .reg .u64 t; cvta.to.shared.u64 t, %1; cvt.u32.u64 %0, t; }" : "=r"(a) : "l"(p));
    return a;
}
static __device__ __forceinline__ void cp16(uint32_t daddr, const void* gptr, bool pred) {
    int sz = pred ? 16 : 0;
    asm volatile("cp.async.ca.shared.global [%0], [%1], 16, %2;"
                 :: "r"(daddr), "l"(gptr), "r"(sz));
}
static __device__ __forceinline__ void mma_f16(float& d0, float& d1, float& d2, float& d3,
                                               uint32_t a0, uint32_t a1, uint32_t a2, uint32_t a3,
                                               uint32_t b0, uint32_t b1) {
    asm volatile("mma.sync.aligned.m16n8k16.row.col.f32.f16.f16.f32 "
                 "{%0,%1,%2,%3}, {%4,%5,%6,%7}, {%8,%9}, {%0,%1,%2,%3};"
                 : "+f"(d0), "+f"(d1), "+f"(d2), "+f"(d3)
                 : "r"(a0), "r"(a1), "r"(a2), "r"(a3), "r"(b0), "r"(b1));
}
#define LDSM4(r0, r1, r2, r3, addr) \
    asm volatile("ldmatrix.sync.aligned.m8n8.x4.shared.b16 {%0,%1,%2,%3}, [%4];" \
                 : "=r"(r0), "=r"(r1), "=r"(r2), "=r"(r3) : "r"(addr))

// ================= pre-processing =================
// x [img][32][4096] -> g_xth [img][p][cin]  (fp16)
__global__ void transpose_x(const float* __restrict__ x) {
    __shared__ float s[32][137];
    const int img = blockIdx.y, p0 = blockIdx.x * 128, t = threadIdx.x;
    const int c8 = t >> 5, pq = t & 31;
    for (int cc = c8; cc < 32; cc += 8) {
        float4 v = *(const float4*)(x + ((size_t)img * 32 + cc) * 4096 + p0 + pq * 4);
        s[cc][pq*4+0] = v.x; s[cc][pq*4+1] = v.y; s[cc][pq*4+2] = v.z; s[cc][pq*4+3] = v.w;
    }
    __syncthreads();
    const int pl = t >> 3, cq = t & 7;
    for (int pp = pl; pp < 128; pp += 32) {
        __half2 h01 = __floats2half2_rn(s[cq*4+0][pp], s[cq*4+1][pp]);
        __half2 h23 = __floats2half2_rn(s[cq*4+2][pp], s[cq*4+3][pp]);
        __half2* dst = (__half2*)(g_xth + ((size_t)img * 4096 + p0 + pp) * 32 + cq * 4);
        dst[0] = h01; dst[1] = h23;
    }
}

// conv0 weights: tile0 [ck][row128][cin32] (W0), tile1 [ck][row64][cin32] (R0), fp16
__global__ void packA0(const float* __restrict__ W0, const float* __restrict__ R0) {
    int idx = blockIdx.x * 256 + threadIdx.x;       // 55296 total
    if (idx >= 9*4096 + 9*2048) return;
    if (idx < 9*4096) {
        const int ck  = idx >> 12;
        const int row = (idx >> 5) & 127;
        const int cin = idx & 31;
        g_A0h[idx] = __float2half_rn(W0[row * 288 + cin * 9 + ck]);
    } else {
        const int i2  = idx - 9*4096;
        const int ck  = i2 >> 11;
        const int row = (i2 >> 5) & 63;
        const int cin = i2 & 31;
        g_A0h[idx] = __float2half_rn(R0[row * 288 + cin * 9 + ck]);
    }
}
__global__ void packA1(const float* __restrict__ W1) {
    int idx = blockIdx.x * 256 + threadIdx.x;       // 73728
    if (idx >= 18*4096) return;
    const int ck  = idx >> 12;
    const int row = (idx >> 5) & 127;
    const int cl  = idx & 31;
    const int tap = ck >> 1;
    const int cin = ((ck & 1) << 5) + cl;
    g_A1h[idx] = __float2half_rn(W1[row * 576 + cin * 9 + tap]);
}

// ================= fp16 HMMA implicit-GEMM conv: halo-B + 4-slot A ring, 1 sync/chunk ====
// CTA: (MFR*32) couts x 128 pixels (2 image rows), 128 threads (4 warps: 2m x 2n).
// B: 4x66-pixel halo (fp16), loaded once per cin-phase; taps read shifted addresses.
// A: 4-slot cp.async ring, prefetch distance 3, wait_group 2 (data always ready).
// Order per chunk: wait -> sync -> prefetch(l+3) -> compute. One barrier per chunk.
#define PIT 40
#define HALO_H (4*66*PIT)             // 10560 halves (21120 B)

template<int MFR, int C, int NCH>
__global__ __launch_bounds__(128, 3) void conv_tc(int which, const float* __restrict__ bias) {
    constexpr int ROWS = MFR * 32;                 // CTA M
    constexpr int ACH  = ROWS * PIT;               // halves per A slot
    constexpr int EPIP = MFR * 32 + 4;

    extern __shared__ __align__(16) float smem_f[];

    const int tid  = threadIdx.x;
    const int lane = tid & 31;
    const int wid  = tid >> 5;
    const int wm   = wid >> 1;        // 0..1
    const int wn   = wid & 1;         // 0..1 = image row within pair

    const __half* Aw; const __half* Xt; float* Y; int m0, CoutS;
    if (which == 0)      { Aw = g_A0h;          Xt = g_xth;      Y = g_y0t; m0 = 0;   CoutS = 192; }
    else if (which == 1) { Aw = g_A0h + 9*4096; Xt = g_xth;      Y = g_y0t; m0 = 128; CoutS = 192; }
    else                 { Aw = g_A1h;          Xt = g_out0tfh;  Y = g_y1t; m0 = 0;   CoutS = 128; }

    const int img = blockIdx.z;
    const int n0  = blockIdx.x * 128;             // pixel base (2 image rows)
    const int y0  = blockIdx.x * 2;
    const __half* Ximg = Xt + (size_t)img * 4096 * C;
    const uint32_t sb  = s2u(smem_f);
    const uint32_t sbH = sb;
    const uint32_t sbA = sb + HALO_H * 2;

    float acc[MFR][8][4];
    #pragma unroll
    for (int a = 0; a < MFR; a++)
        #pragma unroll
        for (int b = 0; b < 8; b++)
            #pragma unroll
            for (int c = 0; c < 4; c++) acc[a][b][c] = 0.0f;

    // zero x-halo columns (px slots 0 and 65): 4 rows x 2 slots x 5 uint4 (40 halves)
    if (tid < 40) {
        const int hr = tid / 10, rest = tid % 10, cs = rest / 5, q = rest % 5;
        const uint4 z = make_uint4(0, 0, 0, 0);
        *(uint4*)((char*)smem_f + ((hr*66 + (cs ? 65 : 0)) * PIT + q * 8) * 2) = z;
    }

    // ---- halo load for cin-phase h: rows y0-1..y0+2, 64 px, 32 halves each ----
    auto load_halo = [&](int h) {
        #pragma unroll
        for (int it = 0; it < 8; it++) {
            const int i  = tid + it * 128;        // 1024 cp16
            const int hr = i >> 8;
            const int rm = i & 255;
            const int px = rm >> 2, q = rm & 3;
            const int yy = y0 - 1 + hr;
            const bool ok = (unsigned)yy < 64u;
            cp16(sbH + ((hr*66 + 1 + px) * PIT + q * 8) * 2,
                 Ximg + ((size_t)(yy * 64 + px)) * C + h * 32 + q * 8, ok);
        }
    };
    // ---- A prefetch for linear chunk l into ring slot (l&3) ----
    auto prefA = [&](int l) {
        if (l >= NCH) return;
        const int ckA = (NCH == 9) ? l : ((l % 9) * 2 + (l / 9));
        const __half* asrc = Aw + (size_t)ckA * (ROWS * 32);
        const uint32_t ab = sbA + (uint32_t)(l & 3) * (ACH * 2);
        #pragma unroll
        for (int it = 0; it < MFR; it++) {     // ROWS*4 cp16 over 128 threads
            const int idx = tid + it * 128;
            const int row = idx >> 2, q = idx & 3;
            cp16(ab + (row * PIT + q * 8) * 2, asrc + row * 32 + q * 8, true);
        }
    };

    // prologue: halo(phase0) + A chunks 0..2, three groups
    load_halo(0);
    prefA(0);
    asm volatile("cp.async.commit_group;" ::: "memory");
    prefA(1);
    asm volatile("cp.async.commit_group;" ::: "memory");
    prefA(2);
    asm volatile("cp.async.commit_group;" ::: "memory");

    // ldmatrix lane-address components (R12-verified): g&1 -> +8 rows, g>>1 -> +8 halves
    const int lg = lane >> 3, li = lane & 7;
    const int mrow = ((lg & 1) << 3) + li;
    const int mcol = (lg >> 1) << 3;              // halves

    for (int l = 0; l < NCH; l++) {
        if (NCH == 18 && l == 9) {
            // phase boundary: drain, reload halo for cin-half 1
            asm volatile("cp.async.wait_group 2;" ::: "memory");
            __syncthreads();                      // all phase-0 halo reads done
            load_halo(1);
            prefA(l + 3);
            asm volatile("cp.async.commit_group;" ::: "memory");
            asm volatile("cp.async.wait_group 0;" ::: "memory");
            __syncthreads();                      // halo visible to all
        } else {
            asm volatile("cp.async.wait_group 2;" ::: "memory");  // chunk l's group done
            __syncthreads();                      // visibility + slot (l-1) fully read
            prefA(l + 3);                         // overwrites slot (l-1)&3 - safe
            asm volatile("cp.async.commit_group;" ::: "memory");
        }

        const int t = (NCH == 9) ? l : (l % 9);
        const int r = t / 3 - 1;
        const int s = t - (t / 3) * 3 - 1;
        const uint32_t a_th = sbA + (uint32_t)(l & 3) * (ACH * 2) +
                              ((wm * (MFR*16) + mrow) * PIT + mcol) * 2;
        const uint32_t b_th = sbH + (((wn + 1 + r) * 66 + 1 + s + mrow) * PIT + mcol) * 2;
        #pragma unroll
        for (int kst = 0; kst < 2; kst++) {
            uint32_t afr[MFR][4];
            #pragma unroll
            for (int mf = 0; mf < MFR; mf++)
                LDSM4(afr[mf][0], afr[mf][1], afr[mf][2], afr[mf][3],
                      a_th + (mf * 16 * PIT + kst * 16) * 2);
            #pragma unroll
            for (int nfp = 0; nfp < 4; nfp++) {
                uint32_t b0, b1, b2, b3;
                LDSM4(b0, b1, b2, b3, b_th + (nfp * 16 * PIT + kst * 16) * 2);
                #pragma unroll
                for (int mf = 0; mf < MFR; mf++) {
                    mma_f16(acc[mf][nfp*2][0],   acc[mf][nfp*2][1],
                            acc[mf][nfp*2][2],   acc[mf][nfp*2][3],
                            afr[mf][0], afr[mf][1], afr[mf][2], afr[mf][3], b0, b2);
                    mma_f16(acc[mf][nfp*2+1][0], acc[mf][nfp*2+1][1],
                            acc[mf][nfp*2+1][2], acc[mf][nfp*2+1][3],
                            afr[mf][0], afr[mf][1], afr[mf][2], afr[mf][3], b1, b3);
                }
            }
        }
    }
    __syncthreads();   // all smem reads done before epilogue reuses the buffer

    // ---- epilogue: two pixel-halves through smem, coalesced stores (R10-12-verified) ----
    {
        float* sm = smem_f;
        float* Yimg = Y + (size_t)img * 4096 * CoutS;
        constexpr int mq = MFR * 8;       // f4 per pixel row
        #pragma unroll
        for (int half = 0; half < 2; half++) {
            if (wn == half) {
                #pragma unroll
                for (int mf = 0; mf < MFR; mf++) {
                    const int r0 = wm * (MFR * 16) + mf * 16 + (lane >> 2);
                    const int c0 = m0 + r0;
                    const float bv0 = (c0     < 128) ? bias[c0]     : 0.0f;
                    const float bv1 = (c0 + 8 < 128) ? bias[c0 + 8] : 0.0f;
                    #pragma unroll
                    for (int nf = 0; nf < 8; nf++) {
                        const int cc = nf * 8 + (lane & 3) * 2;   // 0..63 within half
                        sm[cc       * EPIP + r0]     = acc[mf][nf][0] + bv0;
                        sm[(cc + 1) * EPIP + r0]     = acc[mf][nf][1] + bv0;
                        sm[cc       * EPIP + r0 + 8] = acc[mf][nf][2] + bv1;
                        sm[(cc + 1) * EPIP + r0 + 8] = acc[mf][nf][3] + bv1;
                    }
                }
            }
            __syncthreads();
            for (int idx = tid; idx < 64 * mq; idx += 128) {
                const int pxl = idx / mq;
                const int j   = idx - pxl * mq;
                const float4 v = *(const float4*)&sm[pxl * EPIP + j * 4];
                *(float4*)&Yimg[(size_t)(n0 + half * 64 + pxl) * CoutS + m0 + j * 4] = v;
            }
            __syncthreads();
        }
    }
}

// ================= scans =================
static __device__ __forceinline__ float sigm(float x) { return 1.0f / (1.0f + __expf(-x)); }

// layer0: reads y0t [img][p][192], writes out0t (fp32) + out0tfh (fp16) + h0
__global__ void scan0_kernel(float* __restrict__ out) {
    const int g = blockIdx.x * 256 + threadIdx.x;    // 1,048,576
    const int c = g & 63;
    const int p = (g >> 6) & 4095;
    const int b = g >> 18;
    float h = 0.5f;
    #pragma unroll 1
    for (int t = 0; t < 16; t++) {
        const size_t base = ((size_t)(b * 16 + t) * 4096 + p) * 192;
        const float gate = g_y0t[base + c];
        const float hid  = g_y0t[base + 64 + c];
        const float res  = g_y0t[base + 128 + c];
        const float z  = sigm(gate);
        const float a  = sigm(-gate);
        const float gv = (hid >= 0.0f) ? (hid + 0.5f) : sigm(hid);
        h = a * h + z * gv;
        const float o = h + res;
        const size_t oidx = ((size_t)(b * 16 + t) * 4096 + p) * 64 + c;
        g_out0t  [oidx] = o;
        g_out0tfh[oidx] = __float2half_rn(o);
    }
    out[16777216 + ((size_t)b * 64 + c) * 4096 + p] = h;   // h0 [b][c][p]
}

// layer1: reads y1t [img][p][128] + out0t; writes final out [img][c][p] + h1
__global__ void scan1_kernel(float* __restrict__ out) {
    __shared__ __align__(16) float st[64][68];
    const int t  = threadIdx.x;
    const int pb = blockIdx.x;        // 0..63
    const int b  = blockIdx.y;        // 0..3
    const int p0 = pb * 64;
    const int pl = t >> 2, qb = t & 3;
    const int co = t >> 2, pq = t & 3;
    float h[16];
    #pragma unroll
    for (int i = 0; i < 16; i++) h[i] = 0.5f;

    #pragma unroll 1
    for (int ts = 0; ts < 16; ts++) {
        const int img = b * 16 + ts;
        const size_t rb = (size_t)img * 4096 + p0 + pl;
        #pragma unroll
        for (int j = 0; j < 4; j++) {
            const int c0 = qb * 4 + 16 * j;
            const float4 g4 = *(const float4*)(g_y1t   + rb * 128 + c0);
            const float4 d4 = *(const float4*)(g_y1t   + rb * 128 + 64 + c0);
            const float4 i4 = *(const float4*)(g_out0t + rb * 64 + c0);
            const float gv4[4] = {g4.x, g4.y, g4.z, g4.w};
            const float dv4[4] = {d4.x, d4.y, d4.z, d4.w};
            const float iv4[4] = {i4.x, i4.y, i4.z, i4.w};
            #pragma unroll
            for (int e = 0; e < 4; e++) {
                const float z  = sigm(gv4[e]);
                const float a  = sigm(-gv4[e]);
                const float gg = (dv4[e] >= 0.0f) ? (dv4[e] + 0.5f) : sigm(dv4[e]);
                float hh = a * h[j * 4 + e] + z * gg;
                h[j * 4 + e] = hh;
                st[c0 + e][pl] = hh + iv4[e];
            }
        }
        __syncthreads();
        #pragma unroll
        for (int i = 0; i < 4; i++) {
            const float4 v = *(const float4*)&st[co][pq * 16 + 4 * i];
            *(float4*)(out + ((size_t)img * 64 + co) * 4096 + p0 + pq * 16 + 4 * i) = v;
        }
        __syncthreads();
    }
    #pragma unroll
    for (int j = 0; j < 4; j++)
        #pragma unroll
        for (int e = 0; e < 4; e++)
            st[qb * 4 + 16 * j + e][pl] = h[j * 4 + e];
    __syncthreads();
    #pragma unroll
    for (int i = 0; i < 4; i++) {
        const float4 v = *(const float4*)&st[co][pq * 16 + 4 * i];
        *(float4*)(out + 17825792 + ((size_t)b * 64 + co) * 4096 + p0 + pq * 16 + 4 * i) = v;
    }
}

// ================= launch =================
extern "C" void kernel_launch(void* const* d_in, const int* in_sizes, int n_in,
                              void* d_out, int out_size) {
    const float* x  = (const float*)d_in[0];
    const float* W0 = (const float*)d_in[1];
    const float* b0 = (const float*)d_in[2];
    const float* R0 = (const float*)d_in[3];
    const float* W1 = (const float*)d_in[4];
    const float* b1 = (const float*)d_in[5];
    float* out = (float*)d_out;

    const int smem4 = (HALO_H + 4 * 128 * PIT) * 2;   // 62080 B (>= 64*132*4 epi)
    const int smem2 = (HALO_H + 4 *  64 * PIT) * 2;   // 41600 B
    cudaFuncSetAttribute(conv_tc<4,32,9>,  cudaFuncAttributeMaxDynamicSharedMemorySize, smem4);
    cudaFuncSetAttribute(conv_tc<2,32,9>,  cudaFuncAttributeMaxDynamicSharedMemorySize, smem2);
    cudaFuncSetAttribute(conv_tc<4,64,18>, cudaFuncAttributeMaxDynamicSharedMemorySize, smem4);

    transpose_x<<<dim3(32, 64), 256>>>(x);
    packA0<<<216, 256>>>(W0, R0);
    packA1<<<288, 256>>>(W1);

    conv_tc<4,32,9><<<dim3(32, 1, 64), 128, smem4>>>(0, b0);   // conv0 couts 0..127 (W0)
    conv_tc<2,32,9><<<dim3(32, 1, 64), 128, smem2>>>(1, b0);   // conv0 couts 128..191 (R0)
    scan0_kernel<<<4096, 256>>>(out);
    conv_tc<4,64,18><<<dim3(32, 1, 64), 128, smem4>>>(2, b1);  // conv1
    scan1_kernel<<<dim3(64, 4), 256>>>(out);
}

// round 16
// speedup vs baseline: 1.2038x; 1.1340x over previous
#include <cuda_runtime.h>
#include <cuda_fp16.h>
#include <cstdint>

// ================= scratch (static device globals) =================
__device__ __align__(16) __half g_xth   [64L*4096*32];   // x [img][p][cin], fp16
__device__ __align__(16) __half g_y0th  [64L*4096*192];  // conv0 out [img][p][cout] (gate|hid|res), fp16
__device__ __align__(16) float  g_out0t [64L*4096*64];   // layer0 out (fp32, residual)
__device__ __align__(16) __half g_out0tfh[64L*4096*64];  // layer0 out, fp16 (conv1 B input)
__device__ __align__(16) __half g_y1th  [64L*4096*128];  // conv1 out [img][p][cout] (gate|hid), fp16
__device__ __align__(16) __half g_A0h   [9*4096 + 9*2048]; // conv0 W: [ck][row128][cin32] ++ [ck][row64][cin32]
__device__ __align__(16) __half g_A1h   [18*4096];         // conv1 W: [ck][row128][cin32] (ck = tap*2+half)

// ================= helpers =================
static __device__ __forceinline__ uint32_t s2u(const void* p) {
    uint32_t a;
    asm("{ .reg .u64 t; cvta.to.shared.u64 t, %1; cvt.u32.u64 %0, t; }" : "=r"(a) : "l"(p));
    return a;
}
static __device__ __forceinline__ void cp16(uint32_t daddr, const void* gptr, bool pred) {
    int sz = pred ? 16 : 0;
    asm volatile("cp.async.ca.shared.global [%0], [%1], 16, %2;"
                 :: "r"(daddr), "l"(gptr), "r"(sz));
}
static __device__ __forceinline__ void mma_f16(float& d0, float& d1, float& d2, float& d3,
                                               uint32_t a0, uint32_t a1, uint32_t a2, uint32_t a3,
                                               uint32_t b0, uint32_t b1) {
    asm volatile("mma.sync.aligned.m16n8k16.row.col.f32.f16.f16.f32 "
                 "{%0,%1,%2,%3}, {%4,%5,%6,%7}, {%8,%9}, {%0,%1,%2,%3};"
                 : "+f"(d0), "+f"(d1), "+f"(d2), "+f"(d3)
                 : "r"(a0), "r"(a1), "r"(a2), "r"(a3), "r"(b0), "r"(b1));
}
#define LDSM4(r0, r1, r2, r3, addr) \
    asm volatile("ldmatrix.sync.aligned.m8n8.x4.shared.b16 {%0,%1,%2,%3}, [%4];" \
                 : "=r"(r0), "=r"(r1), "=r"(r2), "=r"(r3) : "r"(addr))

// ================= pre-processing =================
// x [img][32][4096] -> g_xth [img][p][cin]  (fp16)
__global__ void transpose_x(const float* __restrict__ x) {
    __shared__ float s[32][137];
    const int img = blockIdx.y, p0 = blockIdx.x * 128, t = threadIdx.x;
    const int c8 = t >> 5, pq = t & 31;
    for (int cc = c8; cc < 32; cc += 8) {
        float4 v = *(const float4*)(x + ((size_t)img * 32 + cc) * 4096 + p0 + pq * 4);
        s[cc][pq*4+0] = v.x; s[cc][pq*4+1] = v.y; s[cc][pq*4+2] = v.z; s[cc][pq*4+3] = v.w;
    }
    __syncthreads();
    const int pl = t >> 3, cq = t & 7;
    for (int pp = pl; pp < 128; pp += 32) {
        __half2 h01 = __floats2half2_rn(s[cq*4+0][pp], s[cq*4+1][pp]);
        __half2 h23 = __floats2half2_rn(s[cq*4+2][pp], s[cq*4+3][pp]);
        __half2* dst = (__half2*)(g_xth + ((size_t)img * 4096 + p0 + pp) * 32 + cq * 4);
        dst[0] = h01; dst[1] = h23;
    }
}

// conv0 weights: tile0 [ck][row128][cin32] (W0), tile1 [ck][row64][cin32] (R0), fp16
__global__ void packA0(const float* __restrict__ W0, const float* __restrict__ R0) {
    int idx = blockIdx.x * 256 + threadIdx.x;       // 55296 total
    if (idx >= 9*4096 + 9*2048) return;
    if (idx < 9*4096) {
        const int ck  = idx >> 12;
        const int row = (idx >> 5) & 127;
        const int cin = idx & 31;
        g_A0h[idx] = __float2half_rn(W0[row * 288 + cin * 9 + ck]);
    } else {
        const int i2  = idx - 9*4096;
        const int ck  = i2 >> 11;
        const int row = (i2 >> 5) & 63;
        const int cin = i2 & 31;
        g_A0h[idx] = __float2half_rn(R0[row * 288 + cin * 9 + ck]);
    }
}
__global__ void packA1(const float* __restrict__ W1) {
    int idx = blockIdx.x * 256 + threadIdx.x;       // 73728
    if (idx >= 18*4096) return;
    const int ck  = idx >> 12;
    const int row = (idx >> 5) & 127;
    const int cl  = idx & 31;
    const int tap = ck >> 1;
    const int cin = ((ck & 1) << 5) + cl;
    g_A1h[idx] = __float2half_rn(W1[row * 576 + cin * 9 + tap]);
}

// ================= fp16 HMMA implicit-GEMM conv with halo-B (R12 structure) =================
// CTA: (MFR*32) couts x 128 pixels (2 image rows), 128 threads (4 warps: 2m x 2n).
// B: 4x66-pixel halo (fp16), loaded once per cin-phase; taps read shifted addresses.
// A: cp.async double-buffered fp16 smem. Pitch 40 halves (80B, 16B-aligned, conflict-free).
#define PITCH_H 40
#define HALO_H (4*66*PITCH_H)         // 10560 halves (21120 B)

template<int MFR, int C, int NCH>
__global__ __launch_bounds__(128, 3) void conv_tc(int which, const float* __restrict__ bias) {
    constexpr int ROWS = MFR * 32;                 // CTA M
    constexpr int AT_H = ROWS * PITCH_H;           // halves per A buffer
    constexpr int EPIPH = MFR * 32 + 8;            // epilogue pitch (halves)

    extern __shared__ __align__(16) float smem_f[];

    const int tid  = threadIdx.x;
    const int lane = tid & 31;
    const int wid  = tid >> 5;
    const int wm   = wid >> 1;        // 0..1
    const int wn   = wid & 1;         // 0..1 = image row within pair

    const __half* Aw; const __half* Xt; __half* Y; int m0, CoutS;
    if (which == 0)      { Aw = g_A0h;          Xt = g_xth;      Y = g_y0th; m0 = 0;   CoutS = 192; }
    else if (which == 1) { Aw = g_A0h + 9*4096; Xt = g_xth;      Y = g_y0th; m0 = 128; CoutS = 192; }
    else                 { Aw = g_A1h;          Xt = g_out0tfh;  Y = g_y1th; m0 = 0;   CoutS = 128; }

    const int img = blockIdx.z;
    const int n0  = blockIdx.x * 128;             // pixel base (2 image rows)
    const int y0  = blockIdx.x * 2;
    const __half* Ximg = Xt + (size_t)img * 4096 * C;
    const uint32_t sb  = s2u(smem_f);
    const uint32_t sbH = sb;
    const uint32_t sbA = sb + HALO_H * 2;

    float acc[MFR][8][4];
    #pragma unroll
    for (int a = 0; a < MFR; a++)
        #pragma unroll
        for (int b = 0; b < 8; b++)
            #pragma unroll
            for (int c = 0; c < 4; c++) acc[a][b][c] = 0.0f;

    // zero x-halo columns (px slots 0 and 65): 4 rows x 2 slots x 5 uint4 (40 halves)
    if (tid < 40) {
        const int hr = tid / 10, rest = tid % 10, cs = rest / 5, q = rest % 5;
        const uint4 z = make_uint4(0, 0, 0, 0);
        *(uint4*)((char*)smem_f + ((hr*66 + (cs ? 65 : 0)) * PITCH_H + q * 8) * 2) = z;
    }

    // ---- halo load for cin-phase h: rows y0-1..y0+2, 64 px, 32 halves each ----
    auto load_halo = [&](int h) {
        #pragma unroll
        for (int it = 0; it < 8; it++) {
            const int i  = tid + it * 128;        // 1024 cp16
            const int hr = i >> 8;
            const int rm = i & 255;
            const int px = rm >> 2, q = rm & 3;
            const int yy = y0 - 1 + hr;
            const bool ok = (unsigned)yy < 64u;
            cp16(sbH + ((hr*66 + 1 + px) * PITCH_H + q * 8) * 2,
                 Ximg + ((size_t)(yy * 64 + px)) * C + h * 32 + q * 8, ok);
        }
    };
    // ---- A prefetch for linear chunk l into buffer (l&1) ----
    auto prefA = [&](int l) {
        const int t = (NCH == 9) ? l : (l % 9);
        const int h = (NCH == 9) ? 0 : (l / 9);
        const int ckA = (NCH == 9) ? t : (t * 2 + h);
        const __half* asrc = Aw + (size_t)ckA * (ROWS * 32);
        const uint32_t ab = sbA + (uint32_t)(l & 1) * (AT_H * 2);
        #pragma unroll
        for (int it = 0; it < MFR; it++) {     // ROWS*4 cp16 over 128 threads
            const int idx = tid + it * 128;
            const int row = idx >> 2, q = idx & 3;
            cp16(ab + (row * PITCH_H + q * 8) * 2, asrc + row * 32 + q * 8, true);
        }
    };

    load_halo(0);
    prefA(0);
    asm volatile("cp.async.commit_group;" ::: "memory");

    // ldmatrix lane-address components (R12-verified): g&1 -> +8 rows, g>>1 -> +8 halves
    const int lg = lane >> 3, li = lane & 7;
    const int mrow = ((lg & 1) << 3) + li;
    const int mcol = (lg >> 1) << 3;              // halves

    #pragma unroll 1
    for (int l = 0; l < NCH; l++) {
        const int t = (NCH == 9) ? l : (l % 9);
        const bool phase_start = (NCH != 9) && (l == 9);

        if (phase_start) load_halo(1);
        if (l + 1 < NCH) prefA(l + 1);
        asm volatile("cp.async.commit_group;" ::: "memory");
        if (phase_start) asm volatile("cp.async.wait_group 0;" ::: "memory");
        else             asm volatile("cp.async.wait_group 1;" ::: "memory");
        __syncthreads();

        const int r = t / 3 - 1;
        const int s = t - (t / 3) * 3 - 1;
        const uint32_t abase = sbA + (uint32_t)(l & 1) * (AT_H * 2);
        const uint32_t a_th  = abase + ((wm * (MFR*16) + mrow) * PITCH_H + mcol) * 2;
        const uint32_t b_th  = sbH + (((wn + 1 + r) * 66 + 1 + s + mrow) * PITCH_H + mcol) * 2;

        #pragma unroll
        for (int kst = 0; kst < 2; kst++) {        // two k16 steps
            uint32_t afr[MFR][4];
            #pragma unroll
            for (int mf = 0; mf < MFR; mf++)
                LDSM4(afr[mf][0], afr[mf][1], afr[mf][2], afr[mf][3],
                      a_th + (mf * 16 * PITCH_H + kst * 16) * 2);
            #pragma unroll
            for (int nfp = 0; nfp < 4; nfp++) {    // 16 px per x4 (2 n8-tiles)
                uint32_t b0, b1, b2, b3;
                LDSM4(b0, b1, b2, b3, b_th + (nfp * 16 * PITCH_H + kst * 16) * 2);
                #pragma unroll
                for (int mf = 0; mf < MFR; mf++) {
                    mma_f16(acc[mf][nfp*2][0],   acc[mf][nfp*2][1],
                            acc[mf][nfp*2][2],   acc[mf][nfp*2][3],
                            afr[mf][0], afr[mf][1], afr[mf][2], afr[mf][3], b0, b2);
                    mma_f16(acc[mf][nfp*2+1][0], acc[mf][nfp*2+1][1],
                            acc[mf][nfp*2+1][2], acc[mf][nfp*2+1][3],
                            afr[mf][0], afr[mf][1], afr[mf][2], afr[mf][3], b1, b3);
                }
            }
        }
        __syncthreads();
    }

    // ---- epilogue: two pixel-halves through smem (fp16), coalesced uint4 stores ----
    {
        __half* smh = (__half*)smem_f;
        __half* Yimg = Y + (size_t)img * 4096 * CoutS;
        constexpr int mqh = (MFR * 32) / 8;       // uint4 (8 halves) per px row
        #pragma unroll
        for (int half = 0; half < 2; half++) {
            if (wn == half) {
                #pragma unroll
                for (int mf = 0; mf < MFR; mf++) {
                    const int r0 = wm * (MFR * 16) + mf * 16 + (lane >> 2);
                    const int c0 = m0 + r0;
                    const float bv0 = (c0     < 128) ? bias[c0]     : 0.0f;
                    const float bv1 = (c0 + 8 < 128) ? bias[c0 + 8] : 0.0f;
                    #pragma unroll
                    for (int nf = 0; nf < 8; nf++) {
                        const int cc = nf * 8 + (lane & 3) * 2;   // 0..63 within half
                        smh[cc       * EPIPH + r0]     = __float2half_rn(acc[mf][nf][0] + bv0);
                        smh[(cc + 1) * EPIPH + r0]     = __float2half_rn(acc[mf][nf][1] + bv0);
                        smh[cc       * EPIPH + r0 + 8] = __float2half_rn(acc[mf][nf][2] + bv1);
                        smh[(cc + 1) * EPIPH + r0 + 8] = __float2half_rn(acc[mf][nf][3] + bv1);
                    }
                }
            }
            __syncthreads();
            for (int idx = tid; idx < 64 * mqh; idx += 128) {
                const int pxl = idx / mqh;
                const int j   = idx - pxl * mqh;
                const uint4 v = *(const uint4*)&smh[pxl * EPIPH + j * 8];
                *(uint4*)&Yimg[(size_t)(n0 + half * 64 + pxl) * CoutS + m0 + j * 8] = v;
            }
            __syncthreads();
        }
    }
}

// ================= scans =================
static __device__ __forceinline__ float sigm(float x) { return 1.0f / (1.0f + __expf(-x)); }

// layer0: reads y0th (fp16) [img][p][192], writes out0t (fp32) + out0tfh (fp16) + h0
__global__ void scan0_kernel(float* __restrict__ out) {
    const int g = blockIdx.x * 256 + threadIdx.x;    // 1,048,576
    const int c = g & 63;
    const int p = (g >> 6) & 4095;
    const int b = g >> 18;
    float h = 0.5f;
    #pragma unroll 1
    for (int t = 0; t < 16; t++) {
        const size_t base = ((size_t)(b * 16 + t) * 4096 + p) * 192;
        const float gate = __half2float(g_y0th[base + c]);
        const float hid  = __half2float(g_y0th[base + 64 + c]);
        const float res  = __half2float(g_y0th[base + 128 + c]);
        const float z  = sigm(gate);
        const float a  = sigm(-gate);
        const float gv = (hid >= 0.0f) ? (hid + 0.5f) : sigm(hid);
        h = a * h + z * gv;
        const float o = h + res;
        const size_t oidx = ((size_t)(b * 16 + t) * 4096 + p) * 64 + c;
        g_out0t  [oidx] = o;
        g_out0tfh[oidx] = __float2half_rn(o);
    }
    out[16777216 + ((size_t)b * 64 + c) * 4096 + p] = h;   // h0 [b][c][p]
}

// layer1: reads y1th (fp16) [img][p][128] + out0t; writes final out [img][c][p] + h1
__global__ void scan1_kernel(float* __restrict__ out) {
    __shared__ __align__(16) float st[64][68];
    const int t  = threadIdx.x;
    const int pb = blockIdx.x;        // 0..63
    const int b  = blockIdx.y;        // 0..3
    const int p0 = pb * 64;
    const int pl = t >> 2, qb = t & 3;
    const int co = t >> 2, pq = t & 3;
    float h[16];
    #pragma unroll
    for (int i = 0; i < 16; i++) h[i] = 0.5f;

    #pragma unroll 1
    for (int ts = 0; ts < 16; ts++) {
        const int img = b * 16 + ts;
        const size_t rb = (size_t)img * 4096 + p0 + pl;
        #pragma unroll
        for (int j = 0; j < 4; j++) {
            const int c0 = qb * 4 + 16 * j;
            const __half2* gp = (const __half2*)(g_y1th + rb * 128 + c0);
            const __half2* dp = (const __half2*)(g_y1th + rb * 128 + 64 + c0);
            const __half2 ga = gp[0], gb_ = gp[1];
            const __half2 da = dp[0], db_ = dp[1];
            const float4 i4 = *(const float4*)(g_out0t + rb * 64 + c0);
            const float gv4[4] = {__low2float(ga), __high2float(ga),
                                  __low2float(gb_), __high2float(gb_)};
            const float dv4[4] = {__low2float(da), __high2float(da),
                                  __low2float(db_), __high2float(db_)};
            const float iv4[4] = {i4.x, i4.y, i4.z, i4.w};
            #pragma unroll
            for (int e = 0; e < 4; e++) {
                const float z  = sigm(gv4[e]);
                const float a  = sigm(-gv4[e]);
                const float gg = (dv4[e] >= 0.0f) ? (dv4[e] + 0.5f) : sigm(dv4[e]);
                float hh = a * h[j * 4 + e] + z * gg;
                h[j * 4 + e] = hh;
                st[c0 + e][pl] = hh + iv4[e];
            }
        }
        __syncthreads();
        #pragma unroll
        for (int i = 0; i < 4; i++) {
            const float4 v = *(const float4*)&st[co][pq * 16 + 4 * i];
            *(float4*)(out + ((size_t)img * 64 + co) * 4096 + p0 + pq * 16 + 4 * i) = v;
        }
        __syncthreads();
    }
    #pragma unroll
    for (int j = 0; j < 4; j++)
        #pragma unroll
        for (int e = 0; e < 4; e++)
            st[qb * 4 + 16 * j + e][pl] = h[j * 4 + e];
    __syncthreads();
    #pragma unroll
    for (int i = 0; i < 4; i++) {
        const float4 v = *(const float4*)&st[co][pq * 16 + 4 * i];
        *(float4*)(out + 17825792 + ((size_t)b * 64 + co) * 4096 + p0 + pq * 16 + 4 * i) = v;
    }
}

// ================= launch =================
extern "C" void kernel_launch(void* const* d_in, const int* in_sizes, int n_in,
                              void* d_out, int out_size) {
    const float* x  = (const float*)d_in[0];
    const float* W0 = (const float*)d_in[1];
    const float* b0 = (const float*)d_in[2];
    const float* R0 = (const float*)d_in[3];
    const float* W1 = (const float*)d_in[4];
    const float* b1 = (const float*)d_in[5];
    float* out = (float*)d_out;

    const int smem4 = (HALO_H + 2 * 128 * PITCH_H) * 2;   // 41600 B
    const int smem2 = (HALO_H + 2 *  64 * PITCH_H) * 2;   // 31360 B
    cudaFuncSetAttribute(conv_tc<4,32,9>,  cudaFuncAttributeMaxDynamicSharedMemorySize, smem4);
    cudaFuncSetAttribute(conv_tc<2,32,9>,  cudaFuncAttributeMaxDynamicSharedMemorySize, smem2);
    cudaFuncSetAttribute(conv_tc<4,64,18>, cudaFuncAttributeMaxDynamicSharedMemorySize, smem4);

    transpose_x<<<dim3(32, 64), 256>>>(x);
    packA0<<<216, 256>>>(W0, R0);
    packA1<<<288, 256>>>(W1);

    conv_tc<4,32,9><<<dim3(32, 1, 64), 128, smem4>>>(0, b0);   // conv0 couts 0..127 (W0)
    conv_tc<2,32,9><<<dim3(32, 1, 64), 128, smem2>>>(1, b0);   // conv0 couts 128..191 (R0)
    scan0_kernel<<<4096, 256>>>(out);
    conv_tc<4,64,18><<<dim3(32, 1, 64), 128, smem4>>>(2, b1);  // conv1
    scan1_kernel<<<dim3(64, 4), 256>>>(out);
}